// round 3
// baseline (speedup 1.0000x reference)
#include <cuda_runtime.h>
#include <math.h>

#define BT   4
#define LDIM 512
#define NF1  46
#define NF2  44
#define CCH  32
#define KD   64
#define PWROW 109   // F2D + 2*C + 1

// ---------------- device scratch (no allocations allowed) ----------------
__device__ float g_x[BT*CCH*LDIM];
__device__ float g_y[BT*CCH*LDIM];
__device__ float g_embL[BT*LDIM*KD];
__device__ float g_embR[BT*LDIM*KD];
__device__ float g_peh[LDIM*32];

// ---------------- stage 1: 1D projection ----------------
// grid (32, 4) = (channel, bt); 512 threads = l
__global__ void proj1d_kernel(const float* __restrict__ t1d,
                              const float* __restrict__ w,
                              const float* __restrict__ b) {
    int c = blockIdx.x, bt = blockIdx.y, l = threadIdx.x;
    __shared__ float sw[NF1];
    __shared__ float sb;
    if (threadIdx.x < NF1) sw[threadIdx.x] = w[c*NF1 + threadIdx.x];
    if (threadIdx.x == 0)  sb = b[c];
    __syncthreads();
    const float* row = t1d + (bt*LDIM + l)*NF1;
    float acc = sb;
    #pragma unroll
    for (int f = 0; f < NF1; f++) acc = fmaf(sw[f], row[f], acc);
    g_x[(bt*CCH + c)*LDIM + l] = acc;
}

// ---------------- stage 2: conv3 + instance_norm (+residual) + elu ----------------
// phase 0:  g_y = elu(norm(conv(g_x, w)))
// phase 1:  g_x = elu(g_x + norm(conv(g_y, w)))
// grid (32, 4) = (out channel, bt); 512 threads = l
__global__ void conv_norm_kernel(const float* __restrict__ w, int phase) {
    int c = blockIdx.x, bt = blockIdx.y, l = threadIdx.x;
    const float* in  = phase ? g_y : g_x;
    float*       out = phase ? g_x : g_y;

    __shared__ float swt[CCH*3];
    if (threadIdx.x < CCH*3) swt[threadIdx.x] = w[c*CCH*3 + threadIdx.x];
    __syncthreads();

    const float* inb = in + bt*CCH*LDIM;
    float acc = 0.f;
    #pragma unroll 8
    for (int cp = 0; cp < CCH; cp++) {
        const float* r = inb + cp*LDIM;
        float xm = (l > 0)        ? r[l-1] : 0.f;
        float x0 = r[l];
        float xp = (l < LDIM-1)   ? r[l+1] : 0.f;
        acc = fmaf(swt[cp*3+0], xm, acc);
        acc = fmaf(swt[cp*3+1], x0, acc);
        acc = fmaf(swt[cp*3+2], xp, acc);
    }

    // block reduction over 512 values (16 warps)
    float s = acc, s2 = acc*acc;
    #pragma unroll
    for (int off = 16; off > 0; off >>= 1) {
        s  += __shfl_xor_sync(0xffffffffu, s,  off);
        s2 += __shfl_xor_sync(0xffffffffu, s2, off);
    }
    __shared__ float rs[16], rs2[16];
    __shared__ float smean, srstd;
    int wid = threadIdx.x >> 5, lid = threadIdx.x & 31;
    if (lid == 0) { rs[wid] = s; rs2[wid] = s2; }
    __syncthreads();
    if (wid == 0) {
        float a  = (lid < 16) ? rs[lid]  : 0.f;
        float a2 = (lid < 16) ? rs2[lid] : 0.f;
        #pragma unroll
        for (int off = 8; off > 0; off >>= 1) {
            a  += __shfl_xor_sync(0xffffffffu, a,  off);
            a2 += __shfl_xor_sync(0xffffffffu, a2, off);
        }
        if (lid == 0) {
            float mean = a * (1.f/LDIM);
            float var  = a2 * (1.f/LDIM) - mean*mean;
            smean = mean;
            srstd = rsqrtf(var + 1e-5f);
        }
    }
    __syncthreads();

    float v = (acc - smean) * srstd;
    if (phase) v += g_x[(bt*CCH + c)*LDIM + l];   // residual
    out[(bt*CCH + c)*LDIM + l] = (v > 0.f) ? v : expm1f(v);
}

// ---------------- stage 3: emb projections + PE half table ----------------
// <<<512, 256>>> : 131072 threads = bt*L*K
__global__ void emb_pe_kernel(const float* __restrict__ proj_w) {
    int idx = blockIdx.x * blockDim.x + threadIdx.x;

    if (idx < LDIM*32) {            // pe_half[l][m]
        int l = idx >> 5, m = idx & 31;
        int mm = m & 15;
        float dt = expf(-(float)(2*mm) * (logf(10000.f) / 32.f));
        float a = (float)l * dt;
        g_peh[idx] = (m < 16) ? sinf(a) : cosf(a);
    }

    int bt  = idx >> 15;
    int rem = idx & 32767;
    int l = rem >> 6, o = rem & 63;
    const float* xb = g_x + bt*CCH*LDIM;
    const float* pw = proj_w + o*PWROW;
    float aL = 0.f, aR = 0.f;
    #pragma unroll
    for (int cc = 0; cc < CCH; cc++) {
        float xv = xb[cc*LDIM + l];
        aL = fmaf(pw[NF2 + cc],        xv, aL);
        aR = fmaf(pw[NF2 + CCH + cc],  xv, aR);
    }
    g_embL[idx] = aL;
    g_embR[idx] = aR;
}

// ---------------- stage 4: pair kernel (the big one) ----------------
// grid (8, 512, 4) = (j-tile, i, bt); 256 threads; 4j x 4o register tile/thread
__global__ __launch_bounds__(256) void pair_kernel(
    const float* __restrict__ t2d,
    const float* __restrict__ proj_w,
    const float* __restrict__ proj_b,
    float* __restrict__ out)
{
    const int jt  = blockIdx.x;
    const int i   = blockIdx.y;
    const int bt  = blockIdx.z;
    const int tid = threadIdx.x;
    const int j0  = jt * 64;

    __shared__ __align__(16) float sWT[NF2*64];   // W2d^T  [f][o]
    __shared__ __align__(16) float sTT[NF2*64];   // tile^T [f][j_local]
    __shared__ __align__(16) float sEL[64];
    __shared__ __align__(16) float sWS[64];
    __shared__ __align__(16) float sPB[64];
    __shared__ __align__(16) float sPEI[32];

    for (int idx = tid; idx < 64*NF2; idx += 256) {
        int o = idx / NF2, f = idx - o*NF2;
        sWT[f*64 + o] = proj_w[o*PWROW + f];
    }
    const float* tb = t2d + ((size_t)((bt*LDIM + i)*LDIM + j0)) * NF2;
    for (int idx = tid; idx < 64*NF2; idx += 256) {
        int jl = idx / NF2, f = idx - jl*NF2;
        sTT[f*64 + jl] = tb[idx];
    }
    if (tid < 64) {
        sEL[tid] = g_embL[(bt*LDIM + i)*64 + tid];
        sWS[tid] = proj_w[tid*PWROW + (PWROW-1)];
        sPB[tid] = proj_b[tid];
    }
    if (tid < 32) sPEI[tid] = g_peh[i*32 + tid];
    __syncthreads();

    const int oq = tid & 15;     // o quad: o = oq*4 .. oq*4+3
    const int jq = tid >> 4;     // j quad: j_local = jq*4 .. jq*4+3

    unsigned long long acc[4][2];
    #pragma unroll
    for (int a = 0; a < 4; a++) { acc[a][0] = 0ull; acc[a][1] = 0ull; }

    #pragma unroll 4
    for (int f = 0; f < NF2; f++) {
        // two packed f32x2 pairs of weights (o, o+1) and (o+2, o+3)
        const ulonglong2 wd = *(const ulonglong2*)&sWT[f*64 + oq*4];
        const float4      tv = *(const float4*)&sTT[f*64 + jq*4];
        const float tarr[4] = {tv.x, tv.y, tv.z, tv.w};
        #pragma unroll
        for (int jj = 0; jj < 4; jj++) {
            unsigned long long tp;
            asm("mov.b64 %0, {%1, %1};" : "=l"(tp) : "r"(__float_as_uint(tarr[jj])));
            asm("fma.rn.f32x2 %0, %1, %2, %0;" : "+l"(acc[jj][0]) : "l"(tp), "l"(wd.x));
            asm("fma.rn.f32x2 %0, %1, %2, %0;" : "+l"(acc[jj][1]) : "l"(tp), "l"(wd.y));
        }
    }

    const int obase = oq * 4;
    const float4 wsv = *(const float4*)&sWS[obase];
    const float4 pbv = *(const float4*)&sPB[obase];
    const float4 elv = *(const float4*)&sEL[obase];
    const bool usePE = (bt == 0);
    const bool peI   = (obase < 32);
    float4 pei = make_float4(0.f, 0.f, 0.f, 0.f);
    if (usePE && peI) pei = *(const float4*)&sPEI[obase];

    #pragma unroll
    for (int jj = 0; jj < 4; jj++) {
        int j = j0 + jq*4 + jj;
        float sep = logf(fabsf((float)(i - j)) + 1.f);
        const float4 er = *(const float4*)&g_embR[(bt*LDIM + j)*64 + obase];

        float r0, r1, r2, r3;
        {
            unsigned lo, hi;
            asm("mov.b64 {%0, %1}, %2;" : "=r"(lo), "=r"(hi) : "l"(acc[jj][0]));
            r0 = __uint_as_float(lo); r1 = __uint_as_float(hi);
            asm("mov.b64 {%0, %1}, %2;" : "=r"(lo), "=r"(hi) : "l"(acc[jj][1]));
            r2 = __uint_as_float(lo); r3 = __uint_as_float(hi);
        }

        float4 ov;
        ov.x = r0 + elv.x + er.x + sep*wsv.x + pbv.x;
        ov.y = r1 + elv.y + er.y + sep*wsv.y + pbv.y;
        ov.z = r2 + elv.z + er.z + sep*wsv.z + pbv.z;
        ov.w = r3 + elv.w + er.w + sep*wsv.w + pbv.w;

        if (usePE) {
            if (peI) {
                ov.x += pei.x; ov.y += pei.y; ov.z += pei.z; ov.w += pei.w;
            } else {
                const float4 pj = *(const float4*)&g_peh[j*32 + (obase - 32)];
                ov.x += pj.x; ov.y += pj.y; ov.z += pj.z; ov.w += pj.w;
            }
        }

        *(float4*)&out[(size_t)(((bt*LDIM + i)*LDIM + j))*64 + obase] = ov;
    }
}

// ---------------- launch ----------------
extern "C" void kernel_launch(void* const* d_in, const int* in_sizes, int n_in,
                              void* d_out, int out_size) {
    const float* t1d = (const float*)d_in[0];
    const float* t2d = (const float*)d_in[1];
    const float* p1w = (const float*)d_in[2];
    const float* p1b = (const float*)d_in[3];
    const float* c1w = (const float*)d_in[4];
    const float* c2w = (const float*)d_in[5];
    const float* pw  = (const float*)d_in[6];
    const float* pb  = (const float*)d_in[7];
    float* out = (float*)d_out;

    proj1d_kernel<<<dim3(CCH, BT), LDIM>>>(t1d, p1w, p1b);
    for (int blk = 0; blk < 4; blk++) {
        conv_norm_kernel<<<dim3(CCH, BT), LDIM>>>(c1w + blk*CCH*CCH*3, 0);
        conv_norm_kernel<<<dim3(CCH, BT), LDIM>>>(c2w + blk*CCH*CCH*3, 1);
    }
    emb_pe_kernel<<<512, 256>>>(pw);
    pair_kernel<<<dim3(8, LDIM, BT), 256>>>(t2d, pw, pb, out);
}

// round 4
// speedup vs baseline: 1.4161x; 1.4161x over previous
#include <cuda_runtime.h>
#include <math.h>

#define BT   4
#define LDIM 512
#define NF1  46
#define NF2  44
#define CCH  32
#define KD   64
#define PWROW 109   // F2D + 2*C + 1
#define FP   (NF2/2)   // 22 f-pairs

// ---------------- device scratch (no allocations allowed) ----------------
__device__ float g_x[BT*CCH*LDIM];
__device__ float g_y[BT*CCH*LDIM];
__device__ float g_embL[BT*LDIM*KD];
__device__ float g_embR[BT*LDIM*KD];
__device__ float g_peh[LDIM*32];
__device__ float g_W2[FP*128];     // [fp][o*2 + h], h = f parity
__device__ float g_sep[LDIM];      // log(d+1)

// ---------------- stage 1: 1D projection ----------------
// grid (32, 4) = (channel, bt); 512 threads = l
__global__ void proj1d_kernel(const float* __restrict__ t1d,
                              const float* __restrict__ w,
                              const float* __restrict__ b) {
    int c = blockIdx.x, bt = blockIdx.y, l = threadIdx.x;
    __shared__ float sw[NF1];
    __shared__ float sb;
    if (threadIdx.x < NF1) sw[threadIdx.x] = w[c*NF1 + threadIdx.x];
    if (threadIdx.x == 0)  sb = b[c];
    __syncthreads();
    const float2* row = (const float2*)(t1d + (size_t)(bt*LDIM + l)*NF1);
    float acc = sb;
    #pragma unroll
    for (int f2 = 0; f2 < NF1/2; f2++) {
        float2 v = row[f2];
        acc = fmaf(sw[2*f2+0], v.x, acc);
        acc = fmaf(sw[2*f2+1], v.y, acc);
    }
    g_x[(bt*CCH + c)*LDIM + l] = acc;
}

// ---------------- stage 2: conv3 + instance_norm (+residual) + elu ----------------
// grid (32, 4) = (out channel, bt); 512 threads = l
// input staged through smem in two 16-channel halves (32KB each)
__global__ void conv_norm_kernel(const float* __restrict__ w, int phase) {
    int c = blockIdx.x, bt = blockIdx.y, l = threadIdx.x;
    const float* in  = phase ? g_y : g_x;
    float*       out = phase ? g_x : g_y;

    __shared__ float sIn[16*LDIM];       // 32 KB
    __shared__ float swt[CCH*3];
    if (threadIdx.x < CCH*3) swt[threadIdx.x] = w[c*CCH*3 + threadIdx.x];

    const float* inb = in + bt*CCH*LDIM;
    float acc = 0.f;
    #pragma unroll
    for (int half = 0; half < 2; half++) {
        __syncthreads();   // previous reads done (and weight load visible)
        const float4* src = (const float4*)(inb + half*16*LDIM);
        #pragma unroll
        for (int k = 0; k < 4; k++)
            ((float4*)sIn)[threadIdx.x + k*512] = src[threadIdx.x + k*512];
        __syncthreads();
        #pragma unroll
        for (int cp2 = 0; cp2 < 16; cp2++) {
            const float* r = sIn + cp2*LDIM;
            int cp = half*16 + cp2;
            float xm = (l > 0)        ? r[l-1] : 0.f;
            float x0 = r[l];
            float xp = (l < LDIM-1)   ? r[l+1] : 0.f;
            acc = fmaf(swt[cp*3+0], xm, acc);
            acc = fmaf(swt[cp*3+1], x0, acc);
            acc = fmaf(swt[cp*3+2], xp, acc);
        }
    }

    // block reduction over 512 values (16 warps)
    float s = acc, s2 = acc*acc;
    #pragma unroll
    for (int off = 16; off > 0; off >>= 1) {
        s  += __shfl_xor_sync(0xffffffffu, s,  off);
        s2 += __shfl_xor_sync(0xffffffffu, s2, off);
    }
    __shared__ float rs[16], rs2[16];
    __shared__ float smean, srstd;
    int wid = threadIdx.x >> 5, lid = threadIdx.x & 31;
    if (lid == 0) { rs[wid] = s; rs2[wid] = s2; }
    __syncthreads();
    if (wid == 0) {
        float a  = (lid < 16) ? rs[lid]  : 0.f;
        float a2 = (lid < 16) ? rs2[lid] : 0.f;
        #pragma unroll
        for (int off = 8; off > 0; off >>= 1) {
            a  += __shfl_xor_sync(0xffffffffu, a,  off);
            a2 += __shfl_xor_sync(0xffffffffu, a2, off);
        }
        if (lid == 0) {
            float mean = a * (1.f/LDIM);
            float var  = a2 * (1.f/LDIM) - mean*mean;
            smean = mean;
            srstd = rsqrtf(var + 1e-5f);
        }
    }
    __syncthreads();

    float v = (acc - smean) * srstd;
    if (phase) v += g_x[(bt*CCH + c)*LDIM + l];   // residual
    out[(bt*CCH + c)*LDIM + l] = (v > 0.f) ? v : expm1f(v);
}

// ---------------- stage 3: emb projections + PE table + packed W + sep table ----------------
// <<<512, 256>>>
__global__ void emb_pe_kernel(const float* __restrict__ proj_w) {
    int idx = blockIdx.x * blockDim.x + threadIdx.x;

    if (idx < LDIM*32) {            // pe_half[l][m]
        int l = idx >> 5, m = idx & 31;
        int mm = m & 15;
        float dt = expf(-(float)(2*mm) * (logf(10000.f) / 32.f));
        float a = (float)l * dt;
        g_peh[idx] = (m < 16) ? sinf(a) : cosf(a);
    }
    if (idx < FP*128) {             // packed W2d: [fp][o*2+h]
        int fp = idx >> 7, t = idx & 127;
        int o = t >> 1, h = t & 1;
        g_W2[idx] = proj_w[o*PWROW + 2*fp + h];
    }
    if (idx < LDIM) g_sep[idx] = logf((float)idx + 1.f);

    int bt  = idx >> 15;
    int rem = idx & 32767;
    int l = rem >> 6, o = rem & 63;
    const float* xb = g_x + bt*CCH*LDIM;
    const float* pw = proj_w + o*PWROW;
    float aL = 0.f, aR = 0.f;
    #pragma unroll
    for (int cc = 0; cc < CCH; cc++) {
        float xv = xb[cc*LDIM + l];
        aL = fmaf(pw[NF2 + cc],        xv, aL);
        aR = fmaf(pw[NF2 + CCH + cc],  xv, aR);
    }
    g_embL[idx] = aL;
    g_embR[idx] = aR;
}

// ---------------- stage 4: pair kernel ----------------
// grid (8, 512, 4) = (j-tile, i, bt); 256 threads; 4j x 4o per thread
// f32x2 packing over the f-dimension (f-pairs): no splats, no transposes.
__global__ __launch_bounds__(256) void pair_kernel(
    const float* __restrict__ t2d,
    const float* __restrict__ proj_w,
    const float* __restrict__ proj_b,
    float* __restrict__ out)
{
    const int jt  = blockIdx.x;
    const int i   = blockIdx.y;
    const int bt  = blockIdx.z;
    const int tid = threadIdx.x;
    const int j0  = jt * 64;

    __shared__ __align__(16) float sT [64*NF2];   // [jl][f] straight copy
    __shared__ __align__(16) float sW2[FP*128];   // [fp][o*2+h]
    __shared__ __align__(16) float sEL[64];
    __shared__ __align__(16) float sWS[64];
    __shared__ __align__(16) float sPB[64];
    __shared__ __align__(16) float sPEI[32];
    __shared__ float sSEP[64];

    // straight float4 copies — coalesced global, conflict-free smem
    {
        const float4* tsrc = (const float4*)(t2d + ((size_t)((bt*LDIM + i)*LDIM + j0)) * NF2);
        const float4* wsrc = (const float4*)g_W2;
        #pragma unroll
        for (int k = 0; k < 3; k++) {
            int e = tid + k*256;
            if (e < 704) {
                ((float4*)sT )[e] = tsrc[e];
                ((float4*)sW2)[e] = wsrc[e];
            }
        }
    }
    if (tid < 64) {
        sEL[tid]  = g_embL[(bt*LDIM + i)*64 + tid];
        sWS[tid]  = proj_w[tid*PWROW + (PWROW-1)];
        sPB[tid]  = proj_b[tid];
        int d = i - (j0 + tid);
        sSEP[tid] = g_sep[d < 0 ? -d : d];
    }
    if (tid < 32) sPEI[tid] = g_peh[i*32 + tid];
    __syncthreads();

    const int oq = tid & 15;     // o = oq*4 .. oq*4+3
    const int jq = tid >> 4;     // j_local = jq*4 .. jq*4+3

    // acc[jj][oo]: packed (sum over even f, sum over odd f)
    unsigned long long acc[4][4];
    #pragma unroll
    for (int a = 0; a < 4; a++)
        #pragma unroll
        for (int b = 0; b < 4; b++) acc[a][b] = 0ull;

    #pragma unroll
    for (int fp = 0; fp < FP; fp++) {
        // packed weights for o..o+3 at this f-pair
        const ulonglong2 wa = *(const ulonglong2*)&sW2[fp*128 + oq*8];       // o, o+1
        const ulonglong2 wb = *(const ulonglong2*)&sW2[fp*128 + oq*8 + 4];   // o+2, o+3
        #pragma unroll
        for (int jj = 0; jj < 4; jj++) {
            const unsigned long long tp =
                *(const unsigned long long*)&sT[(jq*4 + jj)*NF2 + 2*fp];     // (t[2fp], t[2fp+1])
            asm("fma.rn.f32x2 %0, %1, %2, %0;" : "+l"(acc[jj][0]) : "l"(tp), "l"(wa.x));
            asm("fma.rn.f32x2 %0, %1, %2, %0;" : "+l"(acc[jj][1]) : "l"(tp), "l"(wa.y));
            asm("fma.rn.f32x2 %0, %1, %2, %0;" : "+l"(acc[jj][2]) : "l"(tp), "l"(wb.x));
            asm("fma.rn.f32x2 %0, %1, %2, %0;" : "+l"(acc[jj][3]) : "l"(tp), "l"(wb.y));
        }
    }

    const int obase = oq * 4;
    const float4 wsv = *(const float4*)&sWS[obase];
    const float4 pbv = *(const float4*)&sPB[obase];
    const float4 elv = *(const float4*)&sEL[obase];
    const bool usePE = (bt == 0);
    const bool peI   = (obase < 32);
    float4 pei = make_float4(0.f, 0.f, 0.f, 0.f);
    if (usePE && peI) pei = *(const float4*)&sPEI[obase];

    #pragma unroll
    for (int jj = 0; jj < 4; jj++) {
        int jl = jq*4 + jj;
        int j  = j0 + jl;
        float sep = sSEP[jl];
        const float4 er = *(const float4*)&g_embR[(bt*LDIM + j)*64 + obase];

        float r[4];
        #pragma unroll
        for (int oo = 0; oo < 4; oo++) {
            unsigned lo, hi;
            asm("mov.b64 {%0, %1}, %2;" : "=r"(lo), "=r"(hi) : "l"(acc[jj][oo]));
            r[oo] = __uint_as_float(lo) + __uint_as_float(hi);
        }

        float4 ov;
        ov.x = r[0] + elv.x + er.x + sep*wsv.x + pbv.x;
        ov.y = r[1] + elv.y + er.y + sep*wsv.y + pbv.y;
        ov.z = r[2] + elv.z + er.z + sep*wsv.z + pbv.z;
        ov.w = r[3] + elv.w + er.w + sep*wsv.w + pbv.w;

        if (usePE) {
            if (peI) {
                ov.x += pei.x; ov.y += pei.y; ov.z += pei.z; ov.w += pei.w;
            } else {
                const float4 pj = *(const float4*)&g_peh[j*32 + (obase - 32)];
                ov.x += pj.x; ov.y += pj.y; ov.z += pj.z; ov.w += pj.w;
            }
        }

        *(float4*)&out[(size_t)(((bt*LDIM + i)*LDIM + j))*64 + obase] = ov;
    }
}

// ---------------- launch ----------------
extern "C" void kernel_launch(void* const* d_in, const int* in_sizes, int n_in,
                              void* d_out, int out_size) {
    const float* t1d = (const float*)d_in[0];
    const float* t2d = (const float*)d_in[1];
    const float* p1w = (const float*)d_in[2];
    const float* p1b = (const float*)d_in[3];
    const float* c1w = (const float*)d_in[4];
    const float* c2w = (const float*)d_in[5];
    const float* pw  = (const float*)d_in[6];
    const float* pb  = (const float*)d_in[7];
    float* out = (float*)d_out;

    proj1d_kernel<<<dim3(CCH, BT), LDIM>>>(t1d, p1w, p1b);
    for (int blk = 0; blk < 4; blk++) {
        conv_norm_kernel<<<dim3(CCH, BT), LDIM>>>(c1w + blk*CCH*CCH*3, 0);
        conv_norm_kernel<<<dim3(CCH, BT), LDIM>>>(c2w + blk*CCH*CCH*3, 1);
    }
    emb_pe_kernel<<<512, 256>>>(pw);
    pair_kernel<<<dim3(8, LDIM, BT), 256>>>(t2d, pw, pb, out);
}

// round 5
// speedup vs baseline: 1.5418x; 1.0888x over previous
#include <cuda_runtime.h>
#include <math.h>

#define BT   4
#define LDIM 512
#define NF1  46
#define NF2  44
#define CCH  32
#define KD   64
#define PWROW 109      // F2D + 2*C + 1
#define FP   (NF2/2)   // 22 f-pairs
#define ST_STRIDE (64*NF2)   // floats per tile buffer

// ---------------- device scratch (no allocations allowed) ----------------
__device__ float g_x[BT*CCH*LDIM];
__device__ float g_y[BT*CCH*LDIM];
__device__ float g_embL[BT*LDIM*KD];
__device__ float g_embR[BT*LDIM*KD];
__device__ float g_peh[LDIM*32];
__device__ float g_W2[FP*128];     // [fp][o*2 + h], h = f parity
__device__ float g_sep[LDIM];      // log(d+1)

// ---------------- stage 1: 1D projection ----------------
__global__ void proj1d_kernel(const float* __restrict__ t1d,
                              const float* __restrict__ w,
                              const float* __restrict__ b) {
    int c = blockIdx.x, bt = blockIdx.y, l = threadIdx.x;
    __shared__ float sw[NF1];
    __shared__ float sb;
    if (threadIdx.x < NF1) sw[threadIdx.x] = w[c*NF1 + threadIdx.x];
    if (threadIdx.x == 0)  sb = b[c];
    __syncthreads();
    const float2* row = (const float2*)(t1d + (size_t)(bt*LDIM + l)*NF1);
    float acc = sb;
    #pragma unroll
    for (int f2 = 0; f2 < NF1/2; f2++) {
        float2 v = row[f2];
        acc = fmaf(sw[2*f2+0], v.x, acc);
        acc = fmaf(sw[2*f2+1], v.y, acc);
    }
    g_x[(bt*CCH + c)*LDIM + l] = acc;
}

// ---------------- stage 2: conv3 + instance_norm (+residual) + elu ----------------
// all 32 channels staged at once (64KB dynamic smem), one sync, 4 acc chains
__global__ __launch_bounds__(512) void conv_norm_kernel(const float* __restrict__ w, int phase) {
    extern __shared__ float sIn[];      // 32*512 floats = 64KB
    int c = blockIdx.x, bt = blockIdx.y, l = threadIdx.x;
    const float* in  = phase ? g_y : g_x;
    float*       out = phase ? g_x : g_y;

    __shared__ float swt[CCH*3];
    if (threadIdx.x < CCH*3) swt[threadIdx.x] = w[c*CCH*3 + threadIdx.x];

    const float4* src = (const float4*)(in + bt*CCH*LDIM);
    #pragma unroll
    for (int k = 0; k < 8; k++)
        ((float4*)sIn)[threadIdx.x + k*512] = src[threadIdx.x + k*512];
    __syncthreads();

    float a[4] = {0.f, 0.f, 0.f, 0.f};
    #pragma unroll
    for (int cp = 0; cp < CCH; cp++) {
        const float* r = sIn + cp*LDIM;
        float xm = (l > 0)        ? r[l-1] : 0.f;
        float x0 = r[l];
        float xp = (l < LDIM-1)   ? r[l+1] : 0.f;
        float t  = a[cp & 3];
        t = fmaf(swt[cp*3+0], xm, t);
        t = fmaf(swt[cp*3+1], x0, t);
        t = fmaf(swt[cp*3+2], xp, t);
        a[cp & 3] = t;
    }
    float acc = (a[0] + a[1]) + (a[2] + a[3]);

    // block reduction over 512 values (16 warps)
    float s = acc, s2 = acc*acc;
    #pragma unroll
    for (int off = 16; off > 0; off >>= 1) {
        s  += __shfl_xor_sync(0xffffffffu, s,  off);
        s2 += __shfl_xor_sync(0xffffffffu, s2, off);
    }
    __shared__ float rs[16], rs2[16];
    __shared__ float smean, srstd;
    int wid = threadIdx.x >> 5, lid = threadIdx.x & 31;
    if (lid == 0) { rs[wid] = s; rs2[wid] = s2; }
    __syncthreads();
    if (wid == 0) {
        float aa  = (lid < 16) ? rs[lid]  : 0.f;
        float aa2 = (lid < 16) ? rs2[lid] : 0.f;
        #pragma unroll
        for (int off = 8; off > 0; off >>= 1) {
            aa  += __shfl_xor_sync(0xffffffffu, aa,  off);
            aa2 += __shfl_xor_sync(0xffffffffu, aa2, off);
        }
        if (lid == 0) {
            float mean = aa * (1.f/LDIM);
            float var  = aa2 * (1.f/LDIM) - mean*mean;
            smean = mean;
            srstd = rsqrtf(var + 1e-5f);
        }
    }
    __syncthreads();

    float v = (acc - smean) * srstd;
    if (phase) v += g_x[(bt*CCH + c)*LDIM + l];   // residual
    out[(bt*CCH + c)*LDIM + l] = (v > 0.f) ? v : expm1f(v);
}

// ---------------- stage 3: emb projections + PE table + packed W + sep table ----------------
__global__ void emb_pe_kernel(const float* __restrict__ proj_w) {
    int idx = blockIdx.x * blockDim.x + threadIdx.x;

    if (idx < LDIM*32) {            // pe_half[l][m]
        int l = idx >> 5, m = idx & 31;
        int mm = m & 15;
        float dt = expf(-(float)(2*mm) * (logf(10000.f) / 32.f));
        float a = (float)l * dt;
        g_peh[idx] = (m < 16) ? sinf(a) : cosf(a);
    }
    if (idx < FP*128) {             // packed W2d: [fp][o*2+h]
        int fp = idx >> 7, t = idx & 127;
        int o = t >> 1, h = t & 1;
        g_W2[idx] = proj_w[o*PWROW + 2*fp + h];
    }
    if (idx < LDIM) g_sep[idx] = logf((float)idx + 1.f);

    int bt  = idx >> 15;
    int rem = idx & 32767;
    int l = rem >> 6, o = rem & 63;
    const float* xb = g_x + bt*CCH*LDIM;
    const float* pw = proj_w + o*PWROW;
    float aL = 0.f, aR = 0.f;
    #pragma unroll
    for (int cc = 0; cc < CCH; cc++) {
        float xv = xb[cc*LDIM + l];
        aL = fmaf(pw[NF2 + cc],        xv, aL);
        aR = fmaf(pw[NF2 + CCH + cc],  xv, aR);
    }
    g_embL[idx] = aL;
    g_embR[idx] = aR;
}

// ---------------- stage 4: pair kernel ----------------
// grid (8, 128, 4) = (j-tile, i-group of 4, bt); 256 threads
// weights loaded once per block; t2d tile double-buffered + register-prefetched
__global__ __launch_bounds__(256) void pair_kernel(
    const float* __restrict__ t2d,
    const float* __restrict__ proj_w,
    const float* __restrict__ proj_b,
    float* __restrict__ out)
{
    const int jt  = blockIdx.x;
    const int ig  = blockIdx.y;
    const int bt  = blockIdx.z;
    const int tid = threadIdx.x;
    const int j0  = jt * 64;

    __shared__ __align__(16) float sW2[FP*128];        // 11264 B
    __shared__ __align__(16) float sTb[2*ST_STRIDE];   // 2x 11264 B
    __shared__ __align__(16) float sWS[64];
    __shared__ __align__(16) float sPB[64];

    // one-time loads: weights + first tile (704 float4 each)
    {
        const float4* wsrc = (const float4*)g_W2;
        const float4* tsrc = (const float4*)(t2d + ((size_t)((bt*LDIM + ig*4)*LDIM + j0)) * NF2);
        #pragma unroll
        for (int k = 0; k < 3; k++) {
            int e = tid + k*256;
            if (e < 704) {
                ((float4*)sW2)[e] = wsrc[e];
                ((float4*)sTb)[e] = tsrc[e];
            }
        }
    }
    if (tid < 64) {
        sWS[tid]  = proj_w[tid*PWROW + (PWROW-1)];
        sPB[tid]  = proj_b[tid];
    }
    __syncthreads();

    const int oq = tid & 15;     // o = oq*4 .. oq*4+3
    const int jq = tid >> 4;     // j_local = jq*4 .. jq*4+3
    const int obase = oq * 4;

    const float4 wsv = *(const float4*)&sWS[obase];
    const float4 pbv = *(const float4*)&sPB[obase];
    const bool usePE = (bt == 0);
    const bool peI   = (obase < 32);

    #pragma unroll
    for (int ii = 0; ii < 4; ii++) {
        const int i   = ig*4 + ii;
        const int cur = ii & 1;

        // prefetch next i's tile into registers (overlaps mainloop)
        float4 pre0, pre1, pre2;
        if (ii < 3) {
            const float4* ts = (const float4*)(t2d + ((size_t)((bt*LDIM + i + 1)*LDIM + j0)) * NF2);
            pre0 = ts[tid];
            pre1 = ts[tid + 256];
            if (tid < 192) pre2 = ts[tid + 512];
        }

        // ---- mainloop: 11 iterations of 2 f-pairs ----
        const float* sT = sTb + cur*ST_STRIDE;
        unsigned long long acc[4][4];
        #pragma unroll
        for (int a = 0; a < 4; a++)
            #pragma unroll
            for (int b = 0; b < 4; b++) acc[a][b] = 0ull;

        #pragma unroll
        for (int fp2 = 0; fp2 < 11; fp2++) {
            const ulonglong2 wa0 = *(const ulonglong2*)&sW2[(2*fp2  )*128 + oq*8];
            const ulonglong2 wb0 = *(const ulonglong2*)&sW2[(2*fp2  )*128 + oq*8 + 4];
            const ulonglong2 wa1 = *(const ulonglong2*)&sW2[(2*fp2+1)*128 + oq*8];
            const ulonglong2 wb1 = *(const ulonglong2*)&sW2[(2*fp2+1)*128 + oq*8 + 4];
            #pragma unroll
            for (int jj = 0; jj < 4; jj++) {
                const ulonglong2 tp = *(const ulonglong2*)&sT[(jq*4 + jj)*NF2 + 4*fp2];
                asm("fma.rn.f32x2 %0, %1, %2, %0;" : "+l"(acc[jj][0]) : "l"(tp.x), "l"(wa0.x));
                asm("fma.rn.f32x2 %0, %1, %2, %0;" : "+l"(acc[jj][1]) : "l"(tp.x), "l"(wa0.y));
                asm("fma.rn.f32x2 %0, %1, %2, %0;" : "+l"(acc[jj][2]) : "l"(tp.x), "l"(wb0.x));
                asm("fma.rn.f32x2 %0, %1, %2, %0;" : "+l"(acc[jj][3]) : "l"(tp.x), "l"(wb0.y));
                asm("fma.rn.f32x2 %0, %1, %2, %0;" : "+l"(acc[jj][0]) : "l"(tp.y), "l"(wa1.x));
                asm("fma.rn.f32x2 %0, %1, %2, %0;" : "+l"(acc[jj][1]) : "l"(tp.y), "l"(wa1.y));
                asm("fma.rn.f32x2 %0, %1, %2, %0;" : "+l"(acc[jj][2]) : "l"(tp.y), "l"(wb1.x));
                asm("fma.rn.f32x2 %0, %1, %2, %0;" : "+l"(acc[jj][3]) : "l"(tp.y), "l"(wb1.y));
            }
        }

        // ---- epilogue ----
        const float4 elv = *(const float4*)&g_embL[(bt*LDIM + i)*64 + obase];
        float4 pei = make_float4(0.f, 0.f, 0.f, 0.f);
        if (usePE && peI) pei = *(const float4*)&g_peh[i*32 + obase];

        #pragma unroll
        for (int jj = 0; jj < 4; jj++) {
            int j = j0 + jq*4 + jj;
            int d = i - j;
            float sep = g_sep[d < 0 ? -d : d];
            const float4 er = *(const float4*)&g_embR[(bt*LDIM + j)*64 + obase];

            float r[4];
            #pragma unroll
            for (int oo = 0; oo < 4; oo++) {
                unsigned lo, hi;
                asm("mov.b64 {%0, %1}, %2;" : "=r"(lo), "=r"(hi) : "l"(acc[jj][oo]));
                r[oo] = __uint_as_float(lo) + __uint_as_float(hi);
            }

            float4 ov;
            ov.x = r[0] + elv.x + er.x + sep*wsv.x + pbv.x;
            ov.y = r[1] + elv.y + er.y + sep*wsv.y + pbv.y;
            ov.z = r[2] + elv.z + er.z + sep*wsv.z + pbv.z;
            ov.w = r[3] + elv.w + er.w + sep*wsv.w + pbv.w;

            if (usePE) {
                if (peI) {
                    ov.x += pei.x; ov.y += pei.y; ov.z += pei.z; ov.w += pei.w;
                } else {
                    const float4 pj = *(const float4*)&g_peh[j*32 + (obase - 32)];
                    ov.x += pj.x; ov.y += pj.y; ov.z += pj.z; ov.w += pj.w;
                }
            }

            *(float4*)&out[(size_t)(((bt*LDIM + i)*LDIM + j))*64 + obase] = ov;
        }

        // commit prefetched tile into the other buffer
        if (ii < 3) {
            float4* dst = (float4*)(sTb + (cur ^ 1)*ST_STRIDE);
            dst[tid]       = pre0;
            dst[tid + 256] = pre1;
            if (tid < 192) dst[tid + 512] = pre2;
        }
        __syncthreads();
    }
}

// ---------------- launch ----------------
extern "C" void kernel_launch(void* const* d_in, const int* in_sizes, int n_in,
                              void* d_out, int out_size) {
    const float* t1d = (const float*)d_in[0];
    const float* t2d = (const float*)d_in[1];
    const float* p1w = (const float*)d_in[2];
    const float* p1b = (const float*)d_in[3];
    const float* c1w = (const float*)d_in[4];
    const float* c2w = (const float*)d_in[5];
    const float* pw  = (const float*)d_in[6];
    const float* pb  = (const float*)d_in[7];
    float* out = (float*)d_out;

    const int convSmem = CCH*LDIM*sizeof(float);   // 64 KB
    cudaFuncSetAttribute(conv_norm_kernel,
                         cudaFuncAttributeMaxDynamicSharedMemorySize, convSmem);

    proj1d_kernel<<<dim3(CCH, BT), LDIM>>>(t1d, p1w, p1b);
    for (int blk = 0; blk < 4; blk++) {
        conv_norm_kernel<<<dim3(CCH, BT), LDIM, convSmem>>>(c1w + blk*CCH*CCH*3, 0);
        conv_norm_kernel<<<dim3(CCH, BT), LDIM, convSmem>>>(c2w + blk*CCH*CCH*3, 1);
    }
    emb_pe_kernel<<<512, 256>>>(pw);
    pair_kernel<<<dim3(8, LDIM/4, BT), 256>>>(t2d, pw, pb, out);
}

// round 9
// speedup vs baseline: 1.9770x; 1.2822x over previous
#include <cuda_runtime.h>
#include <math.h>
#include <stdint.h>

#define BT   4
#define LDIM 512
#define NF1  46
#define NF2  44
#define CCH  32
#define KD   64
#define PWROW 109      // F2D + 2*C + 1
#define KPAD 48
#define PITCH 68       // smem A row pitch in floats (68 % 32 == 4 -> conflict-free frags)

// ---------------- device scratch (no allocations allowed) ----------------
__device__ float g_x[BT*CCH*LDIM];
__device__ float g_y[BT*CCH*LDIM];
__device__ float g_embL[BT*LDIM*KD];
__device__ float g_embR[BT*LDIM*KD];
__device__ float g_peh[LDIM*32];
__device__ float g_sep[LDIM];
__device__ float2 g_Bfrag[8*6*32];   // [ntile][kstep][lane] -> (b0,b1), tf32 bits

// ---------------- stage 1: 1D projection ----------------
__global__ void proj1d_kernel(const float* __restrict__ t1d,
                              const float* __restrict__ w,
                              const float* __restrict__ b) {
    int c = blockIdx.x, bt = blockIdx.y, l = threadIdx.x;
    __shared__ float sw[NF1];
    __shared__ float sb;
    if (threadIdx.x < NF1) sw[threadIdx.x] = w[c*NF1 + threadIdx.x];
    if (threadIdx.x == 0)  sb = b[c];
    __syncthreads();
    const float2* row = (const float2*)(t1d + (size_t)(bt*LDIM + l)*NF1);
    float acc = sb;
    #pragma unroll
    for (int f2 = 0; f2 < NF1/2; f2++) {
        float2 v = row[f2];
        acc = fmaf(sw[2*f2+0], v.x, acc);
        acc = fmaf(sw[2*f2+1], v.y, acc);
    }
    g_x[(bt*CCH + c)*LDIM + l] = acc;
}

// ---------------- stage 2: conv3 + instance_norm (+residual) + elu ----------------
// 128 threads, 4 l positions each; float4 LDS per channel
__global__ __launch_bounds__(128) void conv_norm_kernel(const float* __restrict__ w, int phase) {
    extern __shared__ float sIn[];      // 32*512 floats = 64KB
    __shared__ float swt[CCH*3];
    __shared__ float rs[4], rs2[4];
    __shared__ float smean, srstd;

    int c = blockIdx.x, bt = blockIdx.y, t = threadIdx.x;
    const float* in  = phase ? g_y : g_x;
    float*       out = phase ? g_x : g_y;

    if (t < CCH*3) swt[t] = w[c*CCH*3 + t];
    const float4* src = (const float4*)(in + bt*CCH*LDIM);
    #pragma unroll
    for (int k = 0; k < 32; k++)
        ((float4*)sIn)[t + k*128] = src[t + k*128];
    __syncthreads();

    const int l0 = t*4;
    float a0 = 0.f, a1 = 0.f, a2 = 0.f, a3 = 0.f;
    #pragma unroll
    for (int cp = 0; cp < CCH; cp++) {
        const float* r = sIn + cp*LDIM;
        float4 v = *(const float4*)(r + l0);
        float left  = (t > 0)   ? r[l0-1] : 0.f;
        float right = (t < 127) ? r[l0+4] : 0.f;
        float w0 = swt[cp*3], w1 = swt[cp*3+1], w2 = swt[cp*3+2];
        a0 = fmaf(w0, left, fmaf(w1, v.x, fmaf(w2, v.y, a0)));
        a1 = fmaf(w0, v.x,  fmaf(w1, v.y, fmaf(w2, v.z, a1)));
        a2 = fmaf(w0, v.y,  fmaf(w1, v.z, fmaf(w2, v.w, a2)));
        a3 = fmaf(w0, v.z,  fmaf(w1, v.w, fmaf(w2, right, a3)));
    }

    float s  = (a0 + a1) + (a2 + a3);
    float s2 = (a0*a0 + a1*a1) + (a2*a2 + a3*a3);
    #pragma unroll
    for (int off = 16; off > 0; off >>= 1) {
        s  += __shfl_xor_sync(0xffffffffu, s,  off);
        s2 += __shfl_xor_sync(0xffffffffu, s2, off);
    }
    int wid = t >> 5, lid = t & 31;
    if (lid == 0) { rs[wid] = s; rs2[wid] = s2; }
    __syncthreads();
    if (t == 0) {
        float S  = (rs[0]  + rs[1])  + (rs[2]  + rs[3]);
        float S2 = (rs2[0] + rs2[1]) + (rs2[2] + rs2[3]);
        float mean = S * (1.f/LDIM);
        float var  = S2 * (1.f/LDIM) - mean*mean;
        smean = mean;
        srstd = rsqrtf(var + 1e-5f);
    }
    __syncthreads();

    float mean = smean, rstd = srstd;
    float v0 = (a0 - mean)*rstd, v1 = (a1 - mean)*rstd;
    float v2 = (a2 - mean)*rstd, v3 = (a3 - mean)*rstd;
    if (phase) {
        float4 x4 = *(const float4*)(g_x + (bt*CCH + c)*LDIM + l0);
        v0 += x4.x; v1 += x4.y; v2 += x4.z; v3 += x4.w;
    }
    float4 o4;
    o4.x = (v0 > 0.f) ? v0 : expm1f(v0);
    o4.y = (v1 > 0.f) ? v1 : expm1f(v1);
    o4.z = (v2 > 0.f) ? v2 : expm1f(v2);
    o4.w = (v3 > 0.f) ? v3 : expm1f(v3);
    *(float4*)(out + (bt*CCH + c)*LDIM + l0) = o4;
}

__device__ __forceinline__ uint32_t f2tf32(float v) {
    uint32_t r;
    asm("cvt.rna.tf32.f32 %0, %1;" : "=r"(r) : "f"(v));
    return r;
}

// ---------------- stage 3: emb projections + PE + B fragments + sep table ----------------
__global__ void emb_pe_kernel(const float* __restrict__ proj_w) {
    int idx = blockIdx.x * blockDim.x + threadIdx.x;

    if (idx < LDIM*32) {            // pe_half[l][m]
        int l = idx >> 5, m = idx & 31;
        int mm = m & 15;
        float dt = expf(-(float)(2*mm) * (logf(10000.f) / 32.f));
        float a = (float)l * dt;
        g_peh[idx] = (m < 16) ? sinf(a) : cosf(a);
    }
    if (idx < 8*6*32) {             // B fragments, tf32-converted
        int nt = idx / (6*32);
        int ks = (idx / 32) % 6;
        int lane = idx & 31;
        int o  = nt*8 + (lane >> 2);
        int f0 = ks*8 + (lane & 3);
        int f1 = f0 + 4;
        float b0 = (f0 < NF2) ? proj_w[o*PWROW + f0] : 0.f;
        float b1 = (f1 < NF2) ? proj_w[o*PWROW + f1] : 0.f;
        float2 r;
        r.x = __uint_as_float(f2tf32(b0));
        r.y = __uint_as_float(f2tf32(b1));
        g_Bfrag[idx] = r;
    }
    if (idx < LDIM) g_sep[idx] = logf((float)idx + 1.f);

    int bt  = idx >> 15;
    int rem = idx & 32767;
    int l = rem >> 6, o = rem & 63;
    const float* xb = g_x + bt*CCH*LDIM;
    const float* pw = proj_w + o*PWROW;
    float aL = 0.f, aR = 0.f;
    #pragma unroll
    for (int cc = 0; cc < CCH; cc++) {
        float xv = xb[cc*LDIM + l];
        aL = fmaf(pw[NF2 + cc],        xv, aL);
        aR = fmaf(pw[NF2 + CCH + cc],  xv, aR);
    }
    g_embL[idx] = aL;
    g_embR[idx] = aR;
}

// ---------------- stage 4: pair kernel (tf32 mma.sync + fused epilogue) ----------------
// grid (4, 128, 4) = (j-tile of 128, i-group of 4, bt); 256 threads = 8 warps
// warp w handles j rows [w*16, w*16+16); 8 n-tiles of 8 o; K = 48 (6 k-steps)
__global__ __launch_bounds__(256) void pair_mma_kernel(
    const float* __restrict__ t2d,
    const float* __restrict__ proj_w,
    const float* __restrict__ proj_b,
    float* __restrict__ out)
{
    __shared__ __align__(16) float  sA[128*PITCH];   // 34816 B
    __shared__ __align__(16) float2 sB[8*6*32];      // 12288 B
    __shared__ float sWS[64], sPB[64];
    __shared__ float sEL[64], sPEI[32];

    const int jt = blockIdx.x, ig = blockIdx.y, bt = blockIdx.z;
    const int j0 = jt * 128;
    const int tid = threadIdx.x;
    const int w   = tid >> 5, lane = tid & 31;

    // one-time: B fragments + per-o consts
    {
        const float4* bs = (const float4*)g_Bfrag;
        float4* bd = (float4*)sB;
        #pragma unroll
        for (int k = 0; k < 3; k++) bd[tid + k*256] = bs[tid + k*256];
    }
    if (tid < 64) {
        sWS[tid] = proj_w[tid*PWROW + (PWROW-1)];
        sPB[tid] = proj_b[tid];
    }
    // zero K-pad columns 44..47 (written once; mainloop only overwrites 0..43)
    if (tid < 128) *(float4*)&sA[tid*PITCH + 44] = make_float4(0.f, 0.f, 0.f, 0.f);

    // first A tile (i = ig*4), fully coalesced
    {
        const float4* asrc = (const float4*)(t2d + ((size_t)((bt*LDIM + ig*4)*LDIM + j0)) * NF2);
        #pragma unroll
        for (int k = 0; k < 6; k++) {
            int e = tid + k*256;
            if (e < 1408) {
                float4 v = asrc[e];
                int row = e / 11, c = (e - row*11)*4;
                *(float4*)&sA[row*PITCH + c] = v;
            }
        }
    }
    if (tid < 64) sEL[tid] = g_embL[(bt*LDIM + ig*4)*64 + tid];
    if (tid < 32) sPEI[tid] = g_peh[(ig*4)*32 + tid];
    __syncthreads();

    const int g = lane >> 2;        // group id (row within frag)
    const int tg = lane & 3;        // thread in group
    const bool usePE = (bt == 0);

    #pragma unroll
    for (int ii = 0; ii < 4; ii++) {
        const int i = ig*4 + ii;

        // prefetch next i's tile into registers
        float4 pre[6];
        if (ii < 3) {
            const float4* ts = (const float4*)(t2d + ((size_t)((bt*LDIM + i + 1)*LDIM + j0)) * NF2);
            #pragma unroll
            for (int k = 0; k < 6; k++) {
                int e = tid + k*256;
                if (e < 1408) pre[k] = ts[e];
            }
        }

        // ---- MMA mainloop ----
        float acc[8][4];
        #pragma unroll
        for (int nt = 0; nt < 8; nt++)
            #pragma unroll
            for (int q = 0; q < 4; q++) acc[nt][q] = 0.f;

        const float* Arow = sA + (w*16 + g)*PITCH;
        #pragma unroll
        for (int ks = 0; ks < 6; ks++) {
            uint32_t a0 = f2tf32(Arow[ks*8 + tg]);
            uint32_t a1 = f2tf32(Arow[8*PITCH + ks*8 + tg]);
            uint32_t a2 = f2tf32(Arow[ks*8 + tg + 4]);
            uint32_t a3 = f2tf32(Arow[8*PITCH + ks*8 + tg + 4]);
            #pragma unroll
            for (int nt = 0; nt < 8; nt++) {
                float2 bb = sB[(nt*6 + ks)*32 + lane];
                uint32_t b0 = __float_as_uint(bb.x);
                uint32_t b1 = __float_as_uint(bb.y);
                asm volatile(
                    "mma.sync.aligned.m16n8k8.row.col.f32.tf32.tf32.f32 "
                    "{%0,%1,%2,%3}, {%4,%5,%6,%7}, {%8,%9}, {%0,%1,%2,%3};"
                    : "+f"(acc[nt][0]), "+f"(acc[nt][1]), "+f"(acc[nt][2]), "+f"(acc[nt][3])
                    : "r"(a0), "r"(a1), "r"(a2), "r"(a3), "r"(b0), "r"(b1));
            }
        }

        // ---- fused epilogue ----
        const int ocol = tg * 2;
        #pragma unroll
        for (int h = 0; h < 2; h++) {
            const int r = w*16 + g + h*8;
            const int j = j0 + r;
            int dd = i - j; if (dd < 0) dd = -dd;
            const float sep = g_sep[dd];
            const float* erow = g_embR + ((size_t)(bt*LDIM + j))*64;
            float* orow = out + ((size_t)((bt*LDIM + i)*LDIM + j))*64;
            const float* prow = g_peh + j*32;
            #pragma unroll
            for (int nt = 0; nt < 8; nt++) {
                const int o = nt*8 + ocol;
                float2 er = *(const float2*)(erow + o);
                float v0 = acc[nt][h*2+0] + sEL[o]   + er.x + sep*sWS[o]   + sPB[o];
                float v1 = acc[nt][h*2+1] + sEL[o+1] + er.y + sep*sWS[o+1] + sPB[o+1];
                if (usePE) {
                    if (o < 32) { v0 += sPEI[o]; v1 += sPEI[o+1]; }
                    else {
                        float2 p = *(const float2*)(prow + (o - 32));
                        v0 += p.x; v1 += p.y;
                    }
                }
                float2 ov; ov.x = v0; ov.y = v1;
                *(float2*)(orow + o) = ov;
            }
        }

        __syncthreads();
        // commit prefetched tile + next i's sEL/sPEI
        if (ii < 3) {
            #pragma unroll
            for (int k = 0; k < 6; k++) {
                int e = tid + k*256;
                if (e < 1408) {
                    int row = e / 11, c = (e - row*11)*4;
                    *(float4*)&sA[row*PITCH + c] = pre[k];
                }
            }
            if (tid < 64) sEL[tid] = g_embL[(bt*LDIM + i + 1)*64 + tid];
            if (tid < 32) sPEI[tid] = g_peh[(i + 1)*32 + tid];
            __syncthreads();
        }
    }
}

// ---------------- launch ----------------
extern "C" void kernel_launch(void* const* d_in, const int* in_sizes, int n_in,
                              void* d_out, int out_size) {
    const float* t1d = (const float*)d_in[0];
    const float* t2d = (const float*)d_in[1];
    const float* p1w = (const float*)d_in[2];
    const float* p1b = (const float*)d_in[3];
    const float* c1w = (const float*)d_in[4];
    const float* c2w = (const float*)d_in[5];
    const float* pw  = (const float*)d_in[6];
    const float* pb  = (const float*)d_in[7];
    float* out = (float*)d_out;

    const int convSmem = CCH*LDIM*sizeof(float);   // 64 KB
    cudaFuncSetAttribute(conv_norm_kernel,
                         cudaFuncAttributeMaxDynamicSharedMemorySize, convSmem);

    proj1d_kernel<<<dim3(CCH, BT), LDIM>>>(t1d, p1w, p1b);
    for (int blk = 0; blk < 4; blk++) {
        conv_norm_kernel<<<dim3(CCH, BT), 128, convSmem>>>(c1w + blk*CCH*CCH*3, 0);
        conv_norm_kernel<<<dim3(CCH, BT), 128, convSmem>>>(c2w + blk*CCH*CCH*3, 1);
    }
    emb_pe_kernel<<<512, 256>>>(pw);
    pair_mma_kernel<<<dim3(4, LDIM/4, BT), 256>>>(t2d, pw, pb, out);
}

// round 11
// speedup vs baseline: 2.1729x; 1.0991x over previous
#include <cuda_runtime.h>
#include <math.h>
#include <stdint.h>

#define BT   4
#define LDIM 512
#define NF1  46
#define NF2  44
#define CCH  32
#define KD   64
#define PWROW 109      // F2D + 2*C + 1
#define PITCH 68       // smem A row pitch in floats (68 % 32 == 4 -> conflict-free frags)
#define NBLOCKS 128    // trunk grid size (all co-resident)

// ---------------- device scratch (no allocations allowed) ----------------
__device__ float g_x[BT*CCH*LDIM];
__device__ float g_y[BT*CCH*LDIM];
__device__ float g_embL[BT*LDIM*KD];
__device__ float g_embR[BT*LDIM*KD];
__device__ float g_peh[LDIM*32];
__device__ float g_sep[LDIM];
__device__ float2 g_Bfrag[8*6*32];   // [ntile][kstep][lane] -> (b0,b1), tf32 bits
__device__ int    g_ctr[12];         // grid-barrier counters (zeroed per launch)

__device__ __forceinline__ uint32_t f2tf32(float v) {
    uint32_t r;
    asm("cvt.rna.tf32.f32 %0, %1;" : "=r"(r) : "f"(v));
    return r;
}
__device__ __forceinline__ uint32_t smem_u32(const void* p) {
    uint32_t a;
    asm("{ .reg .u64 t; cvta.to.shared.u64 t, %1; cvt.u32.u64 %0, t; }" : "=r"(a) : "l"(p));
    return a;
}
#define CPASYNC(dst, src) asm volatile("cp.async.cg.shared.global [%0], [%1], 16;" :: "r"(dst), "l"(src))
#define CPCOMMIT()        asm volatile("cp.async.commit_group;" ::: "memory")
#define CPWAIT0()         asm volatile("cp.async.wait_group 0;" ::: "memory")

// ---------------- grid barrier (all NBLOCKS blocks resident) ----------------
__device__ __forceinline__ void grid_bar(int s, int tid) {
    __threadfence();
    __syncthreads();
    if (tid == 0) {
        atomicAdd(&g_ctr[s], 1);
        while (*(volatile int*)&g_ctr[s] < NBLOCKS) __nanosleep(32);
        __threadfence();
    }
    __syncthreads();
}

// ================= persistent trunk kernel =================
// grid (32, 4) = (channel, bt); 512 threads = l
__global__ __launch_bounds__(512) void trunk_kernel(
    const float* __restrict__ t1d,
    const float* __restrict__ p1w,
    const float* __restrict__ p1b,
    const float* __restrict__ c1w,
    const float* __restrict__ c2w,
    const float* __restrict__ proj_w)
{
    extern __shared__ float sIn[];      // 32*512 floats = 64KB
    __shared__ float swt[CCH*3];
    __shared__ float rs[16], rs2[16];
    __shared__ float smean, srstd;

    const int c = blockIdx.x, bt = blockIdx.y;
    const int t = threadIdx.x;
    const int bflat = bt*CCH + c;
    const int l = t;

    // ---- stage P: proj1d + independent precomputations ----
    {
        const float2* row = (const float2*)(t1d + (size_t)(bt*LDIM + l)*NF1);
        float acc = __ldg(&p1b[c]);
        #pragma unroll
        for (int f2 = 0; f2 < NF1/2; f2++) {
            float2 v = row[f2];
            acc = fmaf(__ldg(&p1w[c*NF1 + 2*f2]),     v.x, acc);
            acc = fmaf(__ldg(&p1w[c*NF1 + 2*f2 + 1]), v.y, acc);
        }
        g_x[(bt*CCH + c)*LDIM + l] = acc;

        // PE half table: 16384 entries, 128 per block
        if (t < 128) {
            int idx = bflat*128 + t;
            int ll = idx >> 5, m = idx & 31;
            int mm = m & 15;
            float dt = expf(-(float)(2*mm) * (logf(10000.f) / 32.f));
            float a = (float)ll * dt;
            g_peh[idx] = (m < 16) ? sinf(a) : cosf(a);
        }
        // B fragments (1536 entries): block 0
        if (bflat == 0) {
            #pragma unroll
            for (int k = 0; k < 3; k++) {
                int idx = k*512 + t;
                if (idx < 8*6*32) {
                    int nt = idx / (6*32);
                    int ks = (idx / 32) % 6;
                    int lane = idx & 31;
                    int o  = nt*8 + (lane >> 2);
                    int f0 = ks*8 + (lane & 3);
                    int f1 = f0 + 4;
                    float b0 = (f0 < NF2) ? proj_w[o*PWROW + f0] : 0.f;
                    float b1 = (f1 < NF2) ? proj_w[o*PWROW + f1] : 0.f;
                    float2 r;
                    r.x = __uint_as_float(f2tf32(b0));
                    r.y = __uint_as_float(f2tf32(b1));
                    g_Bfrag[idx] = r;
                }
            }
        }
        // sep table: block 1
        if (bflat == 1) g_sep[t] = logf((float)t + 1.f);
    }
    grid_bar(0, t);

    // ---- 8 conv + instance_norm (+residual) + elu stages ----
    for (int s = 0; s < 8; s++) {
        const int phase = s & 1;
        const float* in  = phase ? g_y : g_x;
        float*       outp = phase ? g_x : g_y;
        const float* w = (phase ? c2w : c1w) + (s >> 1)*CCH*CCH*3;

        if (t < CCH*3) swt[t] = w[c*CCH*3 + t];
        const float4* src = (const float4*)(in + bt*CCH*LDIM);
        #pragma unroll
        for (int k = 0; k < 8; k++)
            ((float4*)sIn)[t + k*512] = src[t + k*512];
        __syncthreads();

        float a4[4] = {0.f, 0.f, 0.f, 0.f};
        #pragma unroll 8
        for (int cp = 0; cp < CCH; cp++) {
            const float* r = sIn + cp*LDIM;
            float xm = (l > 0)        ? r[l-1] : 0.f;
            float x0 = r[l];
            float xp = (l < LDIM-1)   ? r[l+1] : 0.f;
            float tt = a4[cp & 3];
            tt = fmaf(swt[cp*3+0], xm, tt);
            tt = fmaf(swt[cp*3+1], x0, tt);
            tt = fmaf(swt[cp*3+2], xp, tt);
            a4[cp & 3] = tt;
        }
        float acc = (a4[0] + a4[1]) + (a4[2] + a4[3]);

        float ss = acc, s2 = acc*acc;
        #pragma unroll
        for (int off = 16; off > 0; off >>= 1) {
            ss += __shfl_xor_sync(0xffffffffu, ss, off);
            s2 += __shfl_xor_sync(0xffffffffu, s2, off);
        }
        int wid = t >> 5, lid = t & 31;
        if (lid == 0) { rs[wid] = ss; rs2[wid] = s2; }
        __syncthreads();
        if (wid == 0) {
            float aa  = (lid < 16) ? rs[lid]  : 0.f;
            float aa2 = (lid < 16) ? rs2[lid] : 0.f;
            #pragma unroll
            for (int off = 8; off > 0; off >>= 1) {
                aa  += __shfl_xor_sync(0xffffffffu, aa,  off);
                aa2 += __shfl_xor_sync(0xffffffffu, aa2, off);
            }
            if (lid == 0) {
                float mean = aa * (1.f/LDIM);
                float var  = aa2 * (1.f/LDIM) - mean*mean;
                smean = mean;
                srstd = rsqrtf(var + 1e-5f);
            }
        }
        __syncthreads();

        float v = (acc - smean) * srstd;
        if (phase) v += g_x[(bt*CCH + c)*LDIM + l];   // residual
        outp[(bt*CCH + c)*LDIM + l] = (v > 0.f) ? v : expm1f(v);

        grid_bar(1 + s, t);
    }

    // ---- final stage: embL / embR projections (2 outputs per thread) ----
    #pragma unroll
    for (int rr = 0; rr < 2; rr++) {
        int idx = bflat*1024 + rr*512 + t;
        int btx = idx >> 15;
        int rem = idx & 32767;
        int ll = rem >> 6, o = rem & 63;
        const float* xb = g_x + btx*CCH*LDIM;
        const float* pw = proj_w + o*PWROW;
        float aL = 0.f, aR = 0.f;
        #pragma unroll
        for (int cc = 0; cc < CCH; cc++) {
            float xv = xb[cc*LDIM + ll];
            aL = fmaf(__ldg(&pw[NF2 + cc]),       xv, aL);
            aR = fmaf(__ldg(&pw[NF2 + CCH + cc]), xv, aR);
        }
        g_embL[idx] = aL;
        g_embR[idx] = aR;
    }
}

// ================= pair kernel (tf32 mma.sync + cp.async + fused epilogue) =================
// grid (4, 128, 4) = (j-tile of 128, i-group of 4, bt); 256 threads = 8 warps
__global__ __launch_bounds__(256) void pair_mma_kernel(
    const float* __restrict__ t2d,
    const float* __restrict__ proj_w,
    const float* __restrict__ proj_b,
    float* __restrict__ out)
{
    extern __shared__ float dsm[];
    float*  sA0 = dsm;                       // 128*PITCH floats
    float*  sA1 = dsm + 128*PITCH;
    float2* sB  = (float2*)(dsm + 2*128*PITCH);   // 8*6*32 float2 = 12288 B
    __shared__ float sWS[64], sPB[64];

    const int jt = blockIdx.x, ig = blockIdx.y, bt = blockIdx.z;
    const int j0 = jt * 128;
    const int tid = threadIdx.x;
    const int w   = tid >> 5, lane = tid & 31;

    // one-time: B fragments + per-o consts + K-pad zeros
    {
        const float4* bs = (const float4*)g_Bfrag;
        float4* bd = (float4*)sB;
        #pragma unroll
        for (int k = 0; k < 3; k++) bd[tid + k*256] = bs[tid + k*256];
    }
    if (tid < 64) {
        sWS[tid] = __ldg(&proj_w[tid*PWROW + (PWROW-1)]);
        sPB[tid] = __ldg(&proj_b[tid]);
    }
    if (tid < 128) {
        *(float4*)&sA0[tid*PITCH + 44] = make_float4(0.f, 0.f, 0.f, 0.f);
        *(float4*)&sA1[tid*PITCH + 44] = make_float4(0.f, 0.f, 0.f, 0.f);
    }

    const uint32_t a0u = smem_u32(sA0);
    const uint32_t a1u = smem_u32(sA1);

    // tile 0 via cp.async
    {
        const float4* asrc = (const float4*)(t2d + ((size_t)((bt*LDIM + ig*4)*LDIM + j0)) * NF2);
        #pragma unroll
        for (int k = 0; k < 6; k++) {
            int e = tid + k*256;
            if (e < 1408) {
                int row = e / 11, cc = (e - row*11)*4;
                CPASYNC(a0u + (uint32_t)(row*PITCH + cc)*4u, asrc + e);
            }
        }
        CPCOMMIT();
    }
    CPWAIT0();
    __syncthreads();

    const int g = lane >> 2;        // row within frag
    const int tg = lane & 3;        // thread in group
    const int ocol = tg * 2;
    const bool usePE = (bt == 0);

    #pragma unroll
    for (int ii = 0; ii < 4; ii++) {
        const int i = ig*4 + ii;
        const float* sA = (ii & 1) ? sA1 : sA0;

        // kick off next tile into the other buffer
        if (ii < 3) {
            uint32_t du = (ii & 1) ? a0u : a1u;
            const float4* ts = (const float4*)(t2d + ((size_t)((bt*LDIM + i + 1)*LDIM + j0)) * NF2);
            #pragma unroll
            for (int k = 0; k < 6; k++) {
                int e = tid + k*256;
                if (e < 1408) {
                    int row = e / 11, cc = (e - row*11)*4;
                    CPASYNC(du + (uint32_t)(row*PITCH + cc)*4u, ts + e);
                }
            }
            CPCOMMIT();
        }

        // ---- MMA mainloop ----
        float acc[8][4];
        #pragma unroll
        for (int nt = 0; nt < 8; nt++)
            #pragma unroll
            for (int q = 0; q < 4; q++) acc[nt][q] = 0.f;

        const float* Arow = sA + (w*16 + g)*PITCH;
        #pragma unroll
        for (int ks = 0; ks < 6; ks++) {
            uint32_t a0 = f2tf32(Arow[ks*8 + tg]);
            uint32_t a1 = f2tf32(Arow[8*PITCH + ks*8 + tg]);
            uint32_t a2 = f2tf32(Arow[ks*8 + tg + 4]);
            uint32_t a3 = f2tf32(Arow[8*PITCH + ks*8 + tg + 4]);
            #pragma unroll
            for (int nt = 0; nt < 8; nt++) {
                float2 bb = sB[(nt*6 + ks)*32 + lane];
                uint32_t b0 = __float_as_uint(bb.x);
                uint32_t b1 = __float_as_uint(bb.y);
                asm volatile(
                    "mma.sync.aligned.m16n8k8.row.col.f32.tf32.tf32.f32 "
                    "{%0,%1,%2,%3}, {%4,%5,%6,%7}, {%8,%9}, {%0,%1,%2,%3};"
                    : "+f"(acc[nt][0]), "+f"(acc[nt][1]), "+f"(acc[nt][2]), "+f"(acc[nt][3])
                    : "r"(a0), "r"(a1), "r"(a2), "r"(a3), "r"(b0), "r"(b1));
            }
        }

        // ---- fused epilogue ----
        const float* elrow = g_embL + ((size_t)(bt*LDIM + i))*64;
        const float* peirow = g_peh + i*32;
        float cbx[8], cby[8];
        #pragma unroll
        for (int nt = 0; nt < 8; nt++) {
            int o = nt*8 + ocol;
            float2 el = *(const float2*)(elrow + o);
            cbx[nt] = el.x + sPB[o];
            cby[nt] = el.y + sPB[o+1];
            if (usePE && nt < 4) {
                float2 p = *(const float2*)(peirow + o);
                cbx[nt] += p.x; cby[nt] += p.y;
            }
        }
        #pragma unroll
        for (int h = 0; h < 2; h++) {
            const int r = w*16 + g + h*8;
            const int j = j0 + r;
            int dd = i - j; if (dd < 0) dd = -dd;
            const float sep = g_sep[dd];
            const float* erow = g_embR + ((size_t)(bt*LDIM + j))*64;
            float* orow = out + ((size_t)((bt*LDIM + i)*LDIM + j))*64;
            const float* prow = g_peh + j*32;
            #pragma unroll
            for (int nt = 0; nt < 8; nt++) {
                const int o = nt*8 + ocol;
                float2 er = *(const float2*)(erow + o);
                float v0 = acc[nt][h*2+0] + cbx[nt] + er.x + sep*sWS[o];
                float v1 = acc[nt][h*2+1] + cby[nt] + er.y + sep*sWS[o+1];
                if (usePE && nt >= 4) {
                    float2 p = *(const float2*)(prow + (o - 32));
                    v0 += p.x; v1 += p.y;
                }
                float2 ov; ov.x = v0; ov.y = v1;
                *(float2*)(orow + o) = ov;
            }
        }

        if (ii < 3) {
            CPWAIT0();
            __syncthreads();
        }
    }
}

// ---------------- launch ----------------
extern "C" void kernel_launch(void* const* d_in, const int* in_sizes, int n_in,
                              void* d_out, int out_size) {
    const float* t1d = (const float*)d_in[0];
    const float* t2d = (const float*)d_in[1];
    const float* p1w = (const float*)d_in[2];
    const float* p1b = (const float*)d_in[3];
    const float* c1w = (const float*)d_in[4];
    const float* c2w = (const float*)d_in[5];
    const float* pw  = (const float*)d_in[6];
    const float* pb  = (const float*)d_in[7];
    float* out = (float*)d_out;

    const int trunkSmem = CCH*LDIM*sizeof(float);              // 64 KB
    const int pairSmem  = (2*128*PITCH)*sizeof(float) + 12288; // 81920 B
    cudaFuncSetAttribute(trunk_kernel,
                         cudaFuncAttributeMaxDynamicSharedMemorySize, trunkSmem);
    cudaFuncSetAttribute(pair_mma_kernel,
                         cudaFuncAttributeMaxDynamicSharedMemorySize, pairSmem);

    void* ctrPtr = nullptr;
    cudaGetSymbolAddress(&ctrPtr, g_ctr);
    cudaMemsetAsync(ctrPtr, 0, 12*sizeof(int));

    trunk_kernel<<<dim3(CCH, BT), 512, trunkSmem>>>(t1d, p1w, p1b, c1w, c2w, pw);
    pair_mma_kernel<<<dim3(4, LDIM/4, BT), 256, pairSmem>>>(t2d, pw, pb, out);
}

// round 12
// speedup vs baseline: 2.3353x; 1.0748x over previous
#include <cuda_runtime.h>
#include <math.h>
#include <stdint.h>

#define BT   4
#define LDIM 512
#define NF1  46
#define NF2  44
#define CCH  32
#define KD   64
#define PWROW 109      // F2D + 2*C + 1
#define PITCH 52       // 52 % 32 == 20 -> fragment rows hit 32 distinct banks

// ---------------- device scratch (no allocations allowed) ----------------
__device__ float g_x[BT*CCH*LDIM];
__device__ float g_y[BT*CCH*LDIM];
__device__ float g_embL[BT*LDIM*KD];
__device__ float g_embR[BT*LDIM*KD];
__device__ float g_peh[LDIM*32];
__device__ float g_sep[LDIM];
__device__ float2 g_Bfrag[8*6*32];   // [ntile][kstep][lane] -> (b0,b1), tf32 bits
__device__ int    g_ctr[40];         // per-bt barrier counters (bt*10 + stage)

__device__ __forceinline__ uint32_t f2tf32(float v) {
    uint32_t r;
    asm("cvt.rna.tf32.f32 %0, %1;" : "=r"(r) : "f"(v));
    return r;
}
__device__ __forceinline__ uint32_t smem_u32(const void* p) {
    uint32_t a;
    asm("{ .reg .u64 t; cvta.to.shared.u64 t, %1; cvt.u32.u64 %0, t; }" : "=r"(a) : "l"(p));
    return a;
}
#define CPASYNC(dst, src) asm volatile("cp.async.cg.shared.global [%0], [%1], 16;" :: "r"(dst), "l"(src))
#define CPCOMMIT()        asm volatile("cp.async.commit_group;" ::: "memory")
#define CPWAIT0()         asm volatile("cp.async.wait_group 0;" ::: "memory")

// ---------------- per-bt grid barrier (32 blocks of one bt) ----------------
__device__ __forceinline__ void bt_bar(int bt, int s, int tid) {
    __threadfence();
    __syncthreads();
    if (tid == 0) {
        int* ctr = &g_ctr[bt*10 + s];
        atomicAdd(ctr, 1);
        while (*(volatile int*)ctr < CCH) __nanosleep(20);
        __threadfence();
    }
    __syncthreads();
}

// ================= persistent trunk kernel =================
// grid (32, 4) = (channel, bt); 512 threads = l
__global__ __launch_bounds__(512) void trunk_kernel(
    const float* __restrict__ t1d,
    const float* __restrict__ p1w,
    const float* __restrict__ p1b,
    const float* __restrict__ c1w,
    const float* __restrict__ c2w,
    const float* __restrict__ proj_w)
{
    extern __shared__ float sIn[];      // 32*512 floats = 64KB
    __shared__ float swt[CCH*3];
    __shared__ float rs[16], rs2[16];
    __shared__ float smean, srstd;

    const int c = blockIdx.x, bt = blockIdx.y;
    const int t = threadIdx.x;
    const int bflat = bt*CCH + c;
    const int l = t;

    // ---- stage P: proj1d + independent precomputations ----
    {
        const float2* row = (const float2*)(t1d + (size_t)(bt*LDIM + l)*NF1);
        float acc = __ldg(&p1b[c]);
        #pragma unroll
        for (int f2 = 0; f2 < NF1/2; f2++) {
            float2 v = row[f2];
            acc = fmaf(__ldg(&p1w[c*NF1 + 2*f2]),     v.x, acc);
            acc = fmaf(__ldg(&p1w[c*NF1 + 2*f2 + 1]), v.y, acc);
        }
        g_x[(bt*CCH + c)*LDIM + l] = acc;

        // PE half table: 16384 entries, 128 per block
        if (t < 128) {
            int idx = bflat*128 + t;
            int ll = idx >> 5, m = idx & 31;
            int mm = m & 15;
            float dt = expf(-(float)(2*mm) * (logf(10000.f) / 32.f));
            float a = (float)ll * dt;
            g_peh[idx] = (m < 16) ? sinf(a) : cosf(a);
        }
        // B fragments (1536 entries): block 0
        if (bflat == 0) {
            #pragma unroll
            for (int k = 0; k < 3; k++) {
                int idx = k*512 + t;
                if (idx < 8*6*32) {
                    int nt = idx / (6*32);
                    int ks = (idx / 32) % 6;
                    int lane = idx & 31;
                    int o  = nt*8 + (lane >> 2);
                    int f0 = ks*8 + (lane & 3);
                    int f1 = f0 + 4;
                    float b0 = (f0 < NF2) ? proj_w[o*PWROW + f0] : 0.f;
                    float b1 = (f1 < NF2) ? proj_w[o*PWROW + f1] : 0.f;
                    float2 r;
                    r.x = __uint_as_float(f2tf32(b0));
                    r.y = __uint_as_float(f2tf32(b1));
                    g_Bfrag[idx] = r;
                }
            }
        }
        // sep table: block 1 of bt 0... use (bt==0,c==1)
        if (bflat == 1) g_sep[t] = logf((float)t + 1.f);
    }
    bt_bar(bt, 0, t);

    // ---- 8 conv + instance_norm (+residual) + elu stages ----
    for (int s = 0; s < 8; s++) {
        const int phase = s & 1;
        const float* in  = phase ? g_y : g_x;
        float*       outp = phase ? g_x : g_y;
        const float* w = (phase ? c2w : c1w) + (s >> 1)*CCH*CCH*3;

        if (t < CCH*3) swt[t] = w[c*CCH*3 + t];
        const float4* src = (const float4*)(in + bt*CCH*LDIM);
        #pragma unroll
        for (int k = 0; k < 8; k++)
            ((float4*)sIn)[t + k*512] = src[t + k*512];
        __syncthreads();

        float a4[4] = {0.f, 0.f, 0.f, 0.f};
        #pragma unroll 8
        for (int cp = 0; cp < CCH; cp++) {
            const float* r = sIn + cp*LDIM;
            float xm = (l > 0)        ? r[l-1] : 0.f;
            float x0 = r[l];
            float xp = (l < LDIM-1)   ? r[l+1] : 0.f;
            float tt = a4[cp & 3];
            tt = fmaf(swt[cp*3+0], xm, tt);
            tt = fmaf(swt[cp*3+1], x0, tt);
            tt = fmaf(swt[cp*3+2], xp, tt);
            a4[cp & 3] = tt;
        }
        float acc = (a4[0] + a4[1]) + (a4[2] + a4[3]);

        float ss = acc, s2 = acc*acc;
        #pragma unroll
        for (int off = 16; off > 0; off >>= 1) {
            ss += __shfl_xor_sync(0xffffffffu, ss, off);
            s2 += __shfl_xor_sync(0xffffffffu, s2, off);
        }
        int wid = t >> 5, lid = t & 31;
        if (lid == 0) { rs[wid] = ss; rs2[wid] = s2; }
        __syncthreads();
        if (wid == 0) {
            float aa  = (lid < 16) ? rs[lid]  : 0.f;
            float aa2 = (lid < 16) ? rs2[lid] : 0.f;
            #pragma unroll
            for (int off = 8; off > 0; off >>= 1) {
                aa  += __shfl_xor_sync(0xffffffffu, aa,  off);
                aa2 += __shfl_xor_sync(0xffffffffu, aa2, off);
            }
            if (lid == 0) {
                float mean = aa * (1.f/LDIM);
                float var  = aa2 * (1.f/LDIM) - mean*mean;
                smean = mean;
                srstd = rsqrtf(var + 1e-5f);
            }
        }
        __syncthreads();

        float v = (acc - smean) * srstd;
        if (phase) v += g_x[(bt*CCH + c)*LDIM + l];   // residual
        outp[(bt*CCH + c)*LDIM + l] = (v > 0.f) ? v : expm1f(v);

        bt_bar(bt, 1 + s, t);
    }

    // ---- final stage: embL / embR projections (2 outputs per thread) ----
    #pragma unroll
    for (int rr = 0; rr < 2; rr++) {
        int idx = bflat*1024 + rr*512 + t;
        int btx = idx >> 15;
        int rem = idx & 32767;
        int ll = rem >> 6, o = rem & 63;
        const float* xb = g_x + btx*CCH*LDIM;
        const float* pw = proj_w + o*PWROW;
        float aL = 0.f, aR = 0.f;
        #pragma unroll
        for (int cc = 0; cc < CCH; cc++) {
            float xv = xb[cc*LDIM + ll];
            aL = fmaf(__ldg(&pw[NF2 + cc]),       xv, aL);
            aR = fmaf(__ldg(&pw[NF2 + CCH + cc]), xv, aR);
        }
        g_embL[idx] = aL;
        g_embR[idx] = aR;
    }
}

// ================= pair kernel (tf32 mma.sync + cp.async + fused epilogue) =================
// grid (4, 128, 4) = (j-tile of 128, i-group of 4, bt); 256 threads = 8 warps
__global__ __launch_bounds__(256, 3) void pair_mma_kernel(
    const float* __restrict__ t2d,
    const float* __restrict__ proj_w,
    const float* __restrict__ proj_b,
    float* __restrict__ out)
{
    extern __shared__ float dsm[];
    float*  sA0 = dsm;                            // 128*PITCH floats
    float*  sA1 = dsm + 128*PITCH;
    float2* sB  = (float2*)(dsm + 2*128*PITCH);   // 8*6*32 float2 = 12288 B
    __shared__ float sWS[64], sPB[64];
    __shared__ float sSEP[LDIM];

    const int jt = blockIdx.x, ig = blockIdx.y, bt = blockIdx.z;
    const int j0 = jt * 128;
    const int tid = threadIdx.x;
    const int w   = tid >> 5, lane = tid & 31;

    // one-time: B fragments + per-o consts + sep table + K-pad zeros
    {
        const float4* bs = (const float4*)g_Bfrag;
        float4* bd = (float4*)sB;
        #pragma unroll
        for (int k = 0; k < 3; k++) bd[tid + k*256] = bs[tid + k*256];
    }
    {
        const float4* ssrc = (const float4*)g_sep;
        float4* sdst = (float4*)sSEP;
        if (tid < 128) sdst[tid] = ssrc[tid];
    }
    if (tid < 64) {
        sWS[tid] = __ldg(&proj_w[tid*PWROW + (PWROW-1)]);
        sPB[tid] = __ldg(&proj_b[tid]);
    }
    if (tid < 128) {
        *(float4*)&sA0[tid*PITCH + 44] = make_float4(0.f, 0.f, 0.f, 0.f);
        *(float4*)&sA1[tid*PITCH + 44] = make_float4(0.f, 0.f, 0.f, 0.f);
    }

    const uint32_t a0u = smem_u32(sA0);
    const uint32_t a1u = smem_u32(sA1);

    // tile 0 via cp.async
    {
        const float4* asrc = (const float4*)(t2d + ((size_t)((bt*LDIM + ig*4)*LDIM + j0)) * NF2);
        #pragma unroll
        for (int k = 0; k < 6; k++) {
            int e = tid + k*256;
            if (e < 1408) {
                int row = e / 11, cc = (e - row*11)*4;
                CPASYNC(a0u + (uint32_t)(row*PITCH + cc)*4u, asrc + e);
            }
        }
        CPCOMMIT();
    }
    CPWAIT0();
    __syncthreads();

    const int g = lane >> 2;        // row within frag
    const int tg = lane & 3;        // thread in group
    const int ocol = tg * 2;
    const bool usePE = (bt == 0);

    #pragma unroll
    for (int ii = 0; ii < 4; ii++) {
        const int i = ig*4 + ii;
        const float* sA = (ii & 1) ? sA1 : sA0;

        // kick off next tile into the other buffer
        if (ii < 3) {
            uint32_t du = (ii & 1) ? a0u : a1u;
            const float4* ts = (const float4*)(t2d + ((size_t)((bt*LDIM + i + 1)*LDIM + j0)) * NF2);
            #pragma unroll
            for (int k = 0; k < 6; k++) {
                int e = tid + k*256;
                if (e < 1408) {
                    int row = e / 11, cc = (e - row*11)*4;
                    CPASYNC(du + (uint32_t)(row*PITCH + cc)*4u, ts + e);
                }
            }
            CPCOMMIT();
        }

        // ---- MMA mainloop ----
        float acc[8][4];
        #pragma unroll
        for (int nt = 0; nt < 8; nt++)
            #pragma unroll
            for (int q = 0; q < 4; q++) acc[nt][q] = 0.f;

        const float* Arow = sA + (w*16 + g)*PITCH;
        #pragma unroll
        for (int ks = 0; ks < 6; ks++) {
            uint32_t a0 = f2tf32(Arow[ks*8 + tg]);
            uint32_t a1 = f2tf32(Arow[8*PITCH + ks*8 + tg]);
            uint32_t a2 = f2tf32(Arow[ks*8 + tg + 4]);
            uint32_t a3 = f2tf32(Arow[8*PITCH + ks*8 + tg + 4]);
            #pragma unroll
            for (int nt = 0; nt < 8; nt++) {
                float2 bb = sB[(nt*6 + ks)*32 + lane];
                uint32_t b0 = __float_as_uint(bb.x);
                uint32_t b1 = __float_as_uint(bb.y);
                asm volatile(
                    "mma.sync.aligned.m16n8k8.row.col.f32.tf32.tf32.f32 "
                    "{%0,%1,%2,%3}, {%4,%5,%6,%7}, {%8,%9}, {%0,%1,%2,%3};"
                    : "+f"(acc[nt][0]), "+f"(acc[nt][1]), "+f"(acc[nt][2]), "+f"(acc[nt][3])
                    : "r"(a0), "r"(a1), "r"(a2), "r"(a3), "r"(b0), "r"(b1));
            }
        }

        // ---- fused epilogue ----
        const float* elrow  = g_embL + ((size_t)(bt*LDIM + i))*64;
        const float* peirow = g_peh + i*32;
        float cbx[8], cby[8];
        #pragma unroll
        for (int nt = 0; nt < 8; nt++) {
            int o = nt*8 + ocol;
            float2 el = *(const float2*)(elrow + o);
            cbx[nt] = el.x + sPB[o];
            cby[nt] = el.y + sPB[o+1];
            if (usePE && nt < 4) {
                float2 p = *(const float2*)(peirow + o);
                cbx[nt] += p.x; cby[nt] += p.y;
            }
        }
        #pragma unroll
        for (int h = 0; h < 2; h++) {
            const int r = w*16 + g + h*8;
            const int j = j0 + r;
            int dd = i - j; if (dd < 0) dd = -dd;
            const float sep = sSEP[dd];
            const float* erow = g_embR + ((size_t)(bt*LDIM + j))*64;
            float* orow = out + ((size_t)((bt*LDIM + i)*LDIM + j))*64;
            const float* prow = g_peh + j*32;
            #pragma unroll
            for (int nt = 0; nt < 8; nt++) {
                const int o = nt*8 + ocol;
                float2 er = *(const float2*)(erow + o);
                float v0 = acc[nt][h*2+0] + cbx[nt] + er.x + sep*sWS[o];
                float v1 = acc[nt][h*2+1] + cby[nt] + er.y + sep*sWS[o+1];
                if (usePE && nt >= 4) {
                    float2 p = *(const float2*)(prow + (o - 32));
                    v0 += p.x; v1 += p.y;
                }
                float2 ov; ov.x = v0; ov.y = v1;
                *(float2*)(orow + o) = ov;
            }
        }

        if (ii < 3) {
            CPWAIT0();
            __syncthreads();
        }
    }
}

// ---------------- launch ----------------
extern "C" void kernel_launch(void* const* d_in, const int* in_sizes, int n_in,
                              void* d_out, int out_size) {
    const float* t1d = (const float*)d_in[0];
    const float* t2d = (const float*)d_in[1];
    const float* p1w = (const float*)d_in[2];
    const float* p1b = (const float*)d_in[3];
    const float* c1w = (const float*)d_in[4];
    const float* c2w = (const float*)d_in[5];
    const float* pw  = (const float*)d_in[6];
    const float* pb  = (const float*)d_in[7];
    float* out = (float*)d_out;

    const int trunkSmem = CCH*LDIM*sizeof(float);              // 64 KB
    const int pairSmem  = (2*128*PITCH)*sizeof(float) + 12288; // 65536 B
    cudaFuncSetAttribute(trunk_kernel,
                         cudaFuncAttributeMaxDynamicSharedMemorySize, trunkSmem);
    cudaFuncSetAttribute(pair_mma_kernel,
                         cudaFuncAttributeMaxDynamicSharedMemorySize, pairSmem);

    void* ctrPtr = nullptr;
    cudaGetSymbolAddress(&ctrPtr, g_ctr);
    cudaMemsetAsync(ctrPtr, 0, 40*sizeof(int));

    trunk_kernel<<<dim3(CCH, BT), 512, trunkSmem>>>(t1d, p1w, p1b, c1w, c2w, pw);
    pair_mma_kernel<<<dim3(4, LDIM/4, BT), 256, pairSmem>>>(t2d, pw, pb, out);
}